// round 10
// baseline (speedup 1.0000x reference)
#include <cuda_runtime.h>
#include <math.h>
#include <float.h>

// ---------------- problem constants ----------------
#define NN   2048
#define DIN  512
#define HID  256
#define NH   4
#define TOPK 6      // k+1
#define MAXD 2048   // no truncation (kNN hubness gives in-degrees in the hundreds)
#define BKK  16

// ---------------- device scratch (static, no allocs; zero-initialized) ----------------
__device__ float g_zero[NN];       // stays all-zero
__device__ float g_sqU[NN];
__device__ float g_XnF[NN*DIN];
__device__ float g_simU[NN*NN];
__device__ float g_simF[NN*NN];
__device__ int   g_tidxU[NN*TOPK];
__device__ float g_tvalU[NN*TOPK];
__device__ int   g_tidxF[NN*TOPK];
__device__ float g_tvalF[NN*TOPK];
__device__ unsigned char g_maskU[NN*NN];
__device__ unsigned char g_maskF[NN*NN];
__device__ int   g_nbrU[NN*MAXD];
__device__ int   g_cntU[NN];
__device__ int   g_nbrF[NN*MAXD];
__device__ int   g_cntF[NN];
__device__ float g_WcatU[DIN*NH*HID];
__device__ float g_WcatF[DIN*NH*HID];
__device__ float g_WhU[NN*NH*HID];
__device__ float g_WhF[NN*NH*HID];
__device__ float g_s1U[NH*NN];
__device__ float g_s2U[NH*NN];
__device__ float g_s1F[NH*NN];
__device__ float g_s2F[NH*NN];
__device__ float g_hidU[NN*NH*HID];
__device__ float g_hidF[NN*NH*HID];
__device__ float g_WhoU[NN*HID];
__device__ float g_WhoF[NN*HID];
__device__ float g_s1oU[NN];
__device__ float g_s2oU[NN];
__device__ float g_s1oF[NN];
__device__ float g_s2oF[NN];
__device__ float g_embU[NN*HID];
__device__ float g_embF[NN*HID];
__device__ float g_pair[NN*512];
__device__ float g_act0[NN*512];
__device__ float g_act1[NN*256];
__device__ float g_act2[NN*128];

// ---------------- SGEMM: double-buffered, FFMA2 (fma.rn.f32x2) inner loop ----------------
// Each f32x2 lane is an IEEE fp32 rn FMA == fmaf, same k-chain order per output
// element as the proven scalar kernel -> bitwise identical results.
// TB=false: C[M,Nn] = A[M,K]*B[K,Nn]; TB=true: C = A[M,K]*B[Nn,K]^T
// EP: 0 none; 1 negd2 = -((sq[row]+sq[col]) - 2*acc); 2 bias+relu
// SYM: grid.x enumerates upper-tri tile pairs; writes tile and mirror.
// blockIdx.z in {0,1} picks the (A,B,C,sq,bias) set.
template<bool TB, int EP, bool SYM, int TBM, int TBN, int TMI, int TNI>
__launch_bounds__(256, 2)
__global__ void sgemm2(const float* __restrict__ A0, const float* __restrict__ B0,
                       float* __restrict__ C0, const float* __restrict__ sq0,
                       const float* __restrict__ bias0,
                       const float* __restrict__ A1, const float* __restrict__ B1,
                       float* __restrict__ C1, const float* __restrict__ sq1,
                       const float* __restrict__ bias1,
                       int M, int Nn, int Kk, int lda, int ldb, int ldc)
{
    static_assert((TBM/TMI)*(TBN/TNI) == 256, "thread count");
    static_assert(TNI % 2 == 0, "pair width");
    const float* A    = blockIdx.z ? A1 : A0;
    const float* B    = blockIdx.z ? B1 : B0;
    float*       C    = blockIdx.z ? C1 : C0;
    const float* sq   = blockIdx.z ? sq1 : sq0;
    const float* bias = blockIdx.z ? bias1 : bias0;

    __shared__ float As[2][BKK][TBM+4];
    __shared__ float Bs[2][BKK][TBN+4];
    const int tid = threadIdx.x;
    int bx = blockIdx.x, by = blockIdx.y;
    if (SYM) {
        int nb = M / TBM;
        int idx = blockIdx.x, bi = 0;
        while (idx >= nb - bi) { idx -= nb - bi; bi++; }
        by = bi; bx = bi + idx;
    }
    const int m0 = by * TBM, n0 = bx * TBN;
    const int tm = (tid / (TBN/TNI)) * TMI;
    const int tn = (tid % (TBN/TNI)) * TNI;

    const int AIT = TBM*BKK/4/256 > 0 ? TBM*BKK/4/256 : 1;
    const int BIT = TBN*BKK/4/256 > 0 ? TBN*BKK/4/256 : 1;
    float4 ra[AIT], rb[BIT];

    auto LOADA = [&](int k0) {
#pragma unroll
        for (int it = 0; it < AIT; it++) {
            int q = tid + it*256;
            int r = q >> 2, c4 = (q & 3) * 4;
            ra[it] = *(const float4*)(A + (size_t)(m0 + r)*lda + k0 + c4);
        }
    };
    auto STOREA = [&](int buf) {
#pragma unroll
        for (int it = 0; it < AIT; it++) {
            int q = tid + it*256;
            int r = q >> 2, c4 = (q & 3) * 4;
            As[buf][c4+0][r] = ra[it].x; As[buf][c4+1][r] = ra[it].y;
            As[buf][c4+2][r] = ra[it].z; As[buf][c4+3][r] = ra[it].w;
        }
    };
    auto LOADB = [&](int k0) {
#pragma unroll
        for (int it = 0; it < BIT; it++) {
            int q = tid + it*256;
            if (!TB) {
                int r = q / (TBN/4), cn = (q % (TBN/4)) * 4;
                rb[it] = *(const float4*)(B + (size_t)(k0 + r)*ldb + n0 + cn);
            } else {
                int r = q >> 2, c4 = (q & 3) * 4;
                rb[it] = *(const float4*)(B + (size_t)(n0 + r)*ldb + k0 + c4);
            }
        }
    };
    auto STOREB = [&](int buf) {
#pragma unroll
        for (int it = 0; it < BIT; it++) {
            int q = tid + it*256;
            if (!TB) {
                int r = q / (TBN/4), cn = (q % (TBN/4)) * 4;
                Bs[buf][r][cn+0] = rb[it].x; Bs[buf][r][cn+1] = rb[it].y;
                Bs[buf][r][cn+2] = rb[it].z; Bs[buf][r][cn+3] = rb[it].w;
            } else {
                int r = q >> 2, c4 = (q & 3) * 4;
                Bs[buf][c4+0][r] = rb[it].x; Bs[buf][c4+1][r] = rb[it].y;
                Bs[buf][c4+2][r] = rb[it].z; Bs[buf][c4+3][r] = rb[it].w;
            }
        }
    };

    // paired accumulators: low lane = even col, high lane = odd col
    unsigned long long acc2[TMI][TNI/2];
#pragma unroll
    for (int i = 0; i < TMI; i++)
#pragma unroll
        for (int j = 0; j < TNI/2; j++) acc2[i][j] = 0ULL;

    auto COMPUTE = [&](int buf) {
#pragma unroll
        for (int k = 0; k < BKK; k++) {
            float a[TMI];
#pragma unroll
            for (int u = 0; u < TMI/4; u++) {
                float4 v = *(const float4*)&As[buf][k][tm + u*4];
                a[u*4+0] = v.x; a[u*4+1] = v.y; a[u*4+2] = v.z; a[u*4+3] = v.w;
            }
            unsigned long long b2[TNI/2];
#pragma unroll
            for (int u = 0; u < TNI/2; u++)
                b2[u] = *(const unsigned long long*)&Bs[buf][k][tn + u*2];
#pragma unroll
            for (int i = 0; i < TMI; i++) {
                unsigned long long a2;
                asm("mov.b64 %0, {%1, %1};" : "=l"(a2) : "r"(__float_as_uint(a[i])));
#pragma unroll
                for (int j = 0; j < TNI/2; j++)
                    asm("fma.rn.f32x2 %0, %1, %2, %3;"
                        : "=l"(acc2[i][j]) : "l"(a2), "l"(b2[j]), "l"(acc2[i][j]));
            }
        }
    };

    LOADA(0); LOADB(0);
    STOREA(0); STOREB(0);
    __syncthreads();
    int buf = 0;
    for (int k0 = BKK; k0 < Kk; k0 += BKK) {
        LOADA(k0); LOADB(k0);
        COMPUTE(buf);
        STOREA(buf ^ 1); STOREB(buf ^ 1);
        __syncthreads();
        buf ^= 1;
    }
    COMPUTE(buf);

#pragma unroll
    for (int i = 0; i < TMI; i++) {
        int row = m0 + tm + i;
#pragma unroll
        for (int jp = 0; jp < TNI/2; jp++) {
            float vv[2];
            vv[0] = __uint_as_float((unsigned)(acc2[i][jp] & 0xFFFFFFFFu));
            vv[1] = __uint_as_float((unsigned)(acc2[i][jp] >> 32));
#pragma unroll
            for (int s = 0; s < 2; s++) {
                int col = n0 + tn + jp*2 + s;
                float v = vv[s];
                if (EP == 1) v = -((sq[row] + sq[col]) - 2.f * v);
                if (EP == 2) { v += bias[col]; v = fmaxf(v, 0.f); }
                C[(size_t)row * ldc + col] = v;
                if (SYM && bx != by) C[(size_t)col * ldc + row] = v;
            }
        }
    }
}

// ---------------- row reductions (PROVEN) ----------------
__global__ void rowsum_sq(const float* __restrict__ X, float* __restrict__ out, int D)
{
    int i = blockIdx.x, tid = threadIdx.x;
    float s = 0.f;
    for (int j = tid; j < D; j += blockDim.x) { float v = X[(size_t)i*D + j]; s = fmaf(v, v, s); }
    __shared__ float r[256];
    r[tid] = s; __syncthreads();
    for (int st = blockDim.x >> 1; st > 0; st >>= 1) { if (tid < st) r[tid] += r[tid + st]; __syncthreads(); }
    if (tid == 0) out[i] = r[0];
}

__global__ void normalize_rows(const float* __restrict__ X, float* __restrict__ Y, int D)
{
    int i = blockIdx.x, tid = threadIdx.x;
    float s = 0.f;
    for (int j = tid; j < D; j += blockDim.x) { float v = X[(size_t)i*D + j]; s = fmaf(v, v, s); }
    __shared__ float r[256];
    r[tid] = s; __syncthreads();
    for (int st = blockDim.x >> 1; st > 0; st >>= 1) { if (tid < st) r[tid] += r[tid + st]; __syncthreads(); }
    float nrm = sqrtf(r[0]);
    for (int j = tid; j < D; j += blockDim.x) Y[(size_t)i*D + j] = X[(size_t)i*D + j] / nrm;
}

// ---------------- deterministic total order: (value desc, index asc) ----------------
__device__ __forceinline__ bool better(float a, int ai, float b, int bi)
{
    return (a > b) || (a == b && ai < bi);
}

// ---------------- single-pass top-6 with float4 loads, z-batched ----------------
// Selection under a total order is processing-order independent -> identical result.
__global__ void top6_onepass(const float* __restrict__ S0, const float* __restrict__ S1,
                             int* __restrict__ oI0, float* __restrict__ oV0,
                             int* __restrict__ oI1, float* __restrict__ oV1)
{
    const float* S = blockIdx.z ? S1 : S0;
    int*   oI = blockIdx.z ? oI1 : oI0;
    float* oV = blockIdx.z ? oV1 : oV0;

    __shared__ float sv[128*TOPK];
    __shared__ int   si[128*TOPK];
    __shared__ int   ch[TOPK];
    __shared__ float rv[128];
    __shared__ int   ri[128];

    int row = blockIdx.x, tid = threadIdx.x;
    const float4* Sr4 = (const float4*)(S + (size_t)row * NN);

    float lv[TOPK]; int li[TOPK];
#pragma unroll
    for (int t = 0; t < TOPK; t++) { lv[t] = -FLT_MAX; li[t] = 0x7FFFFFFF; }

    auto INS = [&](float x, int j) {
        if (better(x, j, lv[TOPK-1], li[TOPK-1])) {
            lv[TOPK-1] = x; li[TOPK-1] = j;
#pragma unroll
            for (int t = TOPK-1; t > 0; t--) {
                if (better(lv[t], li[t], lv[t-1], li[t-1])) {
                    float tv = lv[t]; lv[t] = lv[t-1]; lv[t-1] = tv;
                    int ti = li[t]; li[t] = li[t-1]; li[t-1] = ti;
                } else break;
            }
        }
    };

#pragma unroll
    for (int it = 0; it < NN/4/128; it++) {
        int j4 = tid + it*128;
        float4 v = Sr4[j4];
        int jb = j4 * 4;
        INS(v.x, jb); INS(v.y, jb+1); INS(v.z, jb+2); INS(v.w, jb+3);
    }
#pragma unroll
    for (int t = 0; t < TOPK; t++) { sv[tid*TOPK+t] = lv[t]; si[tid*TOPK+t] = li[t]; }
    __syncthreads();

    for (int t = 0; t < TOPK; t++) {
        float bv = -FLT_MAX; int bi = 0x7FFFFFFF;
#pragma unroll
        for (int u = 0; u < TOPK; u++) {
            int e = tid*TOPK + u;
            int cidx = si[e];
            bool used = false;
            for (int w = 0; w < t; w++) used |= (ch[w] == cidx);
            if (!used && better(sv[e], cidx, bv, bi)) { bv = sv[e]; bi = cidx; }
        }
        rv[tid] = bv; ri[tid] = bi;
        __syncthreads();
        if (tid < 32) {
#pragma unroll
            for (int o = 32; o < 128; o += 32) {
                if (better(rv[tid+o], ri[tid+o], bv, bi)) { bv = rv[tid+o]; bi = ri[tid+o]; }
            }
#pragma unroll
            for (int o = 16; o > 0; o >>= 1) {
                float ov = __shfl_down_sync(0xFFFFFFFFu, bv, o);
                int   oi = __shfl_down_sync(0xFFFFFFFFu, bi, o);
                if (better(ov, oi, bv, bi)) { bv = ov; bi = oi; }
            }
            if (tid == 0) {
                ch[t] = bi;
                oI[row*TOPK + t] = bi;
                oV[row*TOPK + t] = bv;
            }
        }
        __syncthreads();
    }
}

// ---------------- adjacency mask build, z-batched ----------------
__global__ void clear_masks()
{
    int i = blockIdx.x * blockDim.x + threadIdx.x;   // NN*NN/4 words
    ((unsigned int*)g_maskU)[i] = 0u;
    ((unsigned int*)g_maskF)[i] = 0u;
}

__global__ void mark_kernel2(const int* __restrict__ idx0, const float* __restrict__ val0,
                             unsigned char* __restrict__ mask0,
                             const int* __restrict__ idx1, const float* __restrict__ val1,
                             unsigned char* __restrict__ mask1)
{
    const int*   idx  = blockIdx.z ? idx1 : idx0;
    const float* val  = blockIdx.z ? val1 : val0;
    unsigned char* mask = blockIdx.z ? mask1 : mask0;
    int needPos = blockIdx.z;   // food (z=1) requires positive sim
    int i = blockIdx.x * blockDim.x + threadIdx.x;
    if (i >= NN) return;
#pragma unroll
    for (int t = 0; t < TOPK; t++) {
        int j = idx[i*TOPK + t];
        if (j == i) continue;
        if (needPos && !(val[i*TOPK + t] > 0.f)) continue;
        mask[(size_t)i*NN + j] = 1;
        mask[(size_t)j*NN + i] = 1;
    }
}

// ---------------- neighbor list: warp-ballot compaction (ascending), z-batched ----------------
__global__ void collect_kernel2(const unsigned char* __restrict__ mask0,
                                int* __restrict__ nbr0, int* __restrict__ cnt0,
                                const unsigned char* __restrict__ mask1,
                                int* __restrict__ nbr1, int* __restrict__ cnt1)
{
    const unsigned char* mask = blockIdx.z ? mask1 : mask0;
    int* nbr = blockIdx.z ? nbr1 : nbr0;
    int* cnt = blockIdx.z ? cnt1 : cnt0;
    int warp = (blockIdx.x * blockDim.x + threadIdx.x) >> 5;
    int lane = threadIdx.x & 31;
    if (warp >= NN) return;
    const unsigned char* mr = mask + (size_t)warp * NN;
    int c = 0;
    for (int base = 0; base < NN; base += 32) {
        bool m = mr[base + lane] != 0;
        unsigned b = __ballot_sync(0xFFFFFFFFu, m);
        if (m) nbr[(size_t)warp*MAXD + c + __popc(b & ((1u << lane) - 1u))] = base + lane;
        c += __popc(b);
    }
    if (lane == 0) cnt[warp] = c;
}

// ---------------- sparse attention + aggregate + elu (hub-safe, PROVEN), z-batched ----------------
__global__ void att_agg2(const float* __restrict__ Wh0, const float* __restrict__ s10,
                         const float* __restrict__ s20, const int* __restrict__ nbr0,
                         const int* __restrict__ cnt0, float* __restrict__ out0,
                         const float* __restrict__ Wh1, const float* __restrict__ s11,
                         const float* __restrict__ s21, const int* __restrict__ nbr1,
                         const int* __restrict__ cnt1, float* __restrict__ out1,
                         int rowStride, int nheads)
{
    const float* Wh = blockIdx.z ? Wh1 : Wh0;
    const float* s1 = blockIdx.z ? s11 : s10;
    const float* s2 = blockIdx.z ? s21 : s20;
    const int* nbr  = blockIdx.z ? nbr1 : nbr0;
    const int* cnt  = blockIdx.z ? cnt1 : cnt0;
    float* out      = blockIdx.z ? out1 : out0;

    __shared__ int   sidx[MAXD];       // 8 KB
    __shared__ float sw[NH][MAXD];     // 32 KB
    __shared__ float hs[NH];
    int i = blockIdx.x, tid = threadIdx.x;
    int wid = tid >> 5, lane = tid & 31;
    int c = cnt[i];

    for (int t = tid; t < c; t += 256) sidx[t] = nbr[(size_t)i*MAXD + t];
    __syncthreads();

    for (int q = tid; q < nheads*c; q += 256) {
        int h = q / c, t = q - h*c;
        float e = s1[h*NN + i] + s2[h*NN + sidx[t]];
        sw[h][t] = (e >= 0.f) ? e : 0.2f * e;
    }
    __syncthreads();

    if (wid < nheads) {
        int h = wid;
        float m = -FLT_MAX;
        for (int t = lane; t < c; t += 32) m = fmaxf(m, sw[h][t]);
#pragma unroll
        for (int o = 16; o > 0; o >>= 1) m = fmaxf(m, __shfl_xor_sync(0xFFFFFFFFu, m, o));
        float s = 0.f;
        for (int t = lane; t < c; t += 32) { float ex = expf(sw[h][t] - m); sw[h][t] = ex; s += ex; }
#pragma unroll
        for (int o = 16; o > 0; o >>= 1) s += __shfl_xor_sync(0xFFFFFFFFu, s, o);
        if (lane == 0) hs[h] = s;
    }
    __syncthreads();

    for (int q = tid; q < nheads*c; q += 256) {
        int h = q / c, t = q - h*c;
        sw[h][t] /= hs[h];
    }
    __syncthreads();

    for (int h = 0; h < nheads; h++) {
        float acc = 0.f;
#pragma unroll 4
        for (int t = 0; t < c; t++)
            acc = fmaf(sw[h][t], Wh[(size_t)sidx[t]*rowStride + h*HID + tid], acc);
        out[(size_t)i*rowStride + h*HID + tid] = (acc > 0.f) ? acc : expm1f(acc);
    }
}

// ---------------- GAT helper kernels, z-batched ----------------
__global__ void repack_W2(const float* __restrict__ W0, float* __restrict__ Wcat0,
                          const float* __restrict__ W1, float* __restrict__ Wcat1)
{
    const float* W = blockIdx.z ? W1 : W0;
    float* Wcat    = blockIdx.z ? Wcat1 : Wcat0;
    int i = blockIdx.x * blockDim.x + threadIdx.x;
    if (i >= DIN*NH*HID) return;
    int d = i / (NH*HID);
    int r = i % (NH*HID);
    int h = r / HID;
    int f = r % HID;
    Wcat[i] = W[(size_t)h*DIN*HID + (size_t)d*HID + f];
}

__global__ void s1s2_kernel2(const float* __restrict__ WhA, const float* __restrict__ aA,
                             float* __restrict__ s1A, float* __restrict__ s2A,
                             const float* __restrict__ WhB, const float* __restrict__ aB,
                             float* __restrict__ s1B, float* __restrict__ s2B,
                             int rowStride)
{
    const float* Wh = blockIdx.z ? WhB : WhA;
    const float* a  = blockIdx.z ? aB : aA;
    float* s1 = blockIdx.z ? s1B : s1A;
    float* s2 = blockIdx.z ? s2B : s2A;
    int i = blockIdx.x, h = blockIdx.y, f = threadIdx.x;   // 256 threads
    float w = Wh[(size_t)i*rowStride + h*HID + f];
    float v1 = w * a[h*2*HID + f];
    float v2 = w * a[h*2*HID + HID + f];
    __shared__ float r1[256], r2[256];
    r1[f] = v1; r2[f] = v2; __syncthreads();
    for (int st = 128; st > 0; st >>= 1) {
        if (f < st) { r1[f] += r1[f+st]; r2[f] += r2[f+st]; }
        __syncthreads();
    }
    if (f == 0) { s1[h*NN + i] = r1[0]; s2[h*NN + i] = r2[0]; }
}

// ---------------- MLP pieces (PROVEN) ----------------
__global__ void concat_kernel()
{
    int i = blockIdx.x, c = threadIdx.x;   // 512 threads
    g_pair[(size_t)i*512 + c] = (c < HID) ? g_embU[(size_t)i*HID + c]
                                          : g_embF[(size_t)i*HID + (c - HID)];
}

__global__ void mlp_final_kernel(const float* __restrict__ act, const float* __restrict__ W,
                                 const float* __restrict__ b, float* __restrict__ out)
{
    int i = blockIdx.x, tid = threadIdx.x;   // 128 threads
    float v = act[(size_t)i*128 + tid] * W[tid];
    __shared__ float r[128];
    r[tid] = v; __syncthreads();
    for (int st = 64; st > 0; st >>= 1) { if (tid < st) r[tid] += r[tid+st]; __syncthreads(); }
    if (tid == 0) out[i] = r[0] + b[0];
}

// ---------------- host launch ----------------
template <typename T>
static T* sym(const void* s)
{
    void* p = nullptr;
    cudaGetSymbolAddress(&p, s);
    return (T*)p;
}

extern "C" void kernel_launch(void* const* d_in, const int* in_sizes, int n_in,
                              void* d_out, int out_size)
{
    const float* user_nodes = (const float*)d_in[0];
    const float* food_nodes = (const float*)d_in[1];
    const float* user_W_h   = (const float*)d_in[2];
    const float* user_a_h   = (const float*)d_in[3];
    const float* user_W_o   = (const float*)d_in[4];
    const float* user_a_o   = (const float*)d_in[5];
    const float* food_W_h   = (const float*)d_in[6];
    const float* food_a_h   = (const float*)d_in[7];
    const float* food_W_o   = (const float*)d_in[8];
    const float* food_a_o   = (const float*)d_in[9];
    const float* mlp_W0 = (const float*)d_in[10];
    const float* mlp_b0 = (const float*)d_in[11];
    const float* mlp_W1 = (const float*)d_in[12];
    const float* mlp_b1 = (const float*)d_in[13];
    const float* mlp_W2 = (const float*)d_in[14];
    const float* mlp_b2 = (const float*)d_in[15];
    const float* mlp_W3 = (const float*)d_in[16];
    const float* mlp_b3 = (const float*)d_in[17];
    float* out = (float*)d_out;

    float* pZero  = sym<float>(g_zero);
    float* pSqU   = sym<float>(g_sqU);
    float* pXnF   = sym<float>(g_XnF);
    float* pSimU  = sym<float>(g_simU);
    float* pSimF  = sym<float>(g_simF);
    int*   pTidxU = sym<int>(g_tidxU);
    float* pTvalU = sym<float>(g_tvalU);
    int*   pTidxF = sym<int>(g_tidxF);
    float* pTvalF = sym<float>(g_tvalF);
    unsigned char* pMaskU = sym<unsigned char>(g_maskU);
    unsigned char* pMaskF = sym<unsigned char>(g_maskF);
    int*   pNbrU = sym<int>(g_nbrU);
    int*   pCntU = sym<int>(g_cntU);
    int*   pNbrF = sym<int>(g_nbrF);
    int*   pCntF = sym<int>(g_cntF);
    float* pWcatU = sym<float>(g_WcatU);
    float* pWcatF = sym<float>(g_WcatF);
    float* pWhU  = sym<float>(g_WhU);
    float* pWhF  = sym<float>(g_WhF);
    float* pS1U  = sym<float>(g_s1U);
    float* pS2U  = sym<float>(g_s2U);
    float* pS1F  = sym<float>(g_s1F);
    float* pS2F  = sym<float>(g_s2F);
    float* pHidU = sym<float>(g_hidU);
    float* pHidF = sym<float>(g_hidF);
    float* pWhoU = sym<float>(g_WhoU);
    float* pWhoF = sym<float>(g_WhoF);
    float* pS1oU = sym<float>(g_s1oU);
    float* pS2oU = sym<float>(g_s2oU);
    float* pS1oF = sym<float>(g_s1oF);
    float* pS2oF = sym<float>(g_s2oF);
    float* pEmbU = sym<float>(g_embU);
    float* pEmbF = sym<float>(g_embF);
    float* pPair = sym<float>(g_pair);
    float* pAct0 = sym<float>(g_act0);
    float* pAct1 = sym<float>(g_act1);
    float* pAct2 = sym<float>(g_act2);

    const int NTRI = (NN/128) * (NN/128 + 1) / 2;   // 136 upper-tri tiles

    // ---- graph build ----
    rowsum_sq<<<NN, 256>>>(user_nodes, pSqU, DIN);
    normalize_rows<<<NN, 256>>>(food_nodes, pXnF, DIN);
    // batched sims: z=0 user euclid (-d^2), z=1 food cosine scaled by exact 2x (sq=0)
    sgemm2<true, 1, true, 128,128,8,8><<<dim3(NTRI,1,2), 256>>>(
        user_nodes, user_nodes, pSimU, pSqU, nullptr,
        pXnF,       pXnF,       pSimF, pZero, nullptr,
        NN, NN, DIN, DIN, DIN, NN);
    top6_onepass<<<dim3(NN,1,2), 128>>>(pSimU, pSimF, pTidxU, pTvalU, pTidxF, pTvalF);

    clear_masks<<<(NN*NN/4)/256, 256>>>();
    mark_kernel2<<<dim3((NN+255)/256,1,2), 256>>>(pTidxU, pTvalU, pMaskU,
                                                  pTidxF, pTvalF, pMaskF);
    collect_kernel2<<<dim3(NN*32/256,1,2), 256>>>(pMaskU, pNbrU, pCntU,
                                                  pMaskF, pNbrF, pCntF);

    // ---- GAT hidden layer (user & food batched) ----
    repack_W2<<<dim3((DIN*NH*HID+255)/256,1,2), 256>>>(user_W_h, pWcatU, food_W_h, pWcatF);
    sgemm2<false, 0, false, 128,128,8,8><<<dim3((NH*HID)/128, NN/128, 2), 256>>>(
        user_nodes, pWcatU, pWhU, nullptr, nullptr,
        food_nodes, pWcatF, pWhF, nullptr, nullptr,
        NN, NH*HID, DIN, DIN, NH*HID, NH*HID);
    s1s2_kernel2<<<dim3(NN, NH, 2), 256>>>(pWhU, user_a_h, pS1U, pS2U,
                                           pWhF, food_a_h, pS1F, pS2F, NH*HID);
    att_agg2<<<dim3(NN,1,2), 256>>>(pWhU, pS1U, pS2U, pNbrU, pCntU, pHidU,
                                    pWhF, pS1F, pS2F, pNbrF, pCntF, pHidF,
                                    NH*HID, NH);

    // ---- GAT output layer (user & food batched) ----
    sgemm2<false, 0, false, 64,64,4,4><<<dim3(HID/64, NN/64, 2), 256>>>(
        pHidU, user_W_o, pWhoU, nullptr, nullptr,
        pHidF, food_W_o, pWhoF, nullptr, nullptr,
        NN, HID, NH*HID, NH*HID, HID, HID);
    s1s2_kernel2<<<dim3(NN, 1, 2), 256>>>(pWhoU, user_a_o, pS1oU, pS2oU,
                                          pWhoF, food_a_o, pS1oF, pS2oF, HID);
    att_agg2<<<dim3(NN,1,2), 256>>>(pWhoU, pS1oU, pS2oU, pNbrU, pCntU, pEmbU,
                                    pWhoF, pS1oF, pS2oF, pNbrF, pCntF, pEmbF,
                                    HID, 1);

    // ---- MLP ----
    concat_kernel<<<NN, 512>>>();
    sgemm2<false, 2, false, 64,64,4,4><<<dim3(512/64, NN/64, 1), 256>>>(
        pPair, mlp_W0, pAct0, nullptr, mlp_b0,
        pPair, mlp_W0, pAct0, nullptr, mlp_b0,
        NN, 512, 512, 512, 512, 512);
    sgemm2<false, 2, false, 64,64,4,4><<<dim3(256/64, NN/64, 1), 256>>>(
        pAct0, mlp_W1, pAct1, nullptr, mlp_b1,
        pAct0, mlp_W1, pAct1, nullptr, mlp_b1,
        NN, 256, 512, 512, 256, 256);
    sgemm2<false, 2, false, 64,64,4,4><<<dim3(128/64, NN/64, 1), 256>>>(
        pAct1, mlp_W2, pAct2, nullptr, mlp_b2,
        pAct1, mlp_W2, pAct2, nullptr, mlp_b2,
        NN, 128, 256, 256, 128, 128);
    mlp_final_kernel<<<NN, 128>>>(pAct2, mlp_W3, mlp_b3, out);
}

// round 11
// speedup vs baseline: 1.0108x; 1.0108x over previous
#include <cuda_runtime.h>
#include <math.h>
#include <float.h>

// ---------------- problem constants ----------------
#define NN   2048
#define DIN  512
#define HID  256
#define NH   4
#define TOPK 6      // k+1
#define MAXD 2048   // no truncation (kNN hubness gives in-degrees in the hundreds)
#define BKK  16

// ---------------- device scratch (static, no allocs; zero-initialized) ----------------
__device__ float g_zero[NN];       // stays all-zero
__device__ float g_sqU[NN];
__device__ float g_XnF[NN*DIN];
__device__ float g_simU[NN*NN];
__device__ float g_simF[NN*NN];
__device__ int   g_tidxU[NN*TOPK];
__device__ float g_tvalU[NN*TOPK];
__device__ int   g_tidxF[NN*TOPK];
__device__ float g_tvalF[NN*TOPK];
__device__ unsigned char g_maskU[NN*NN];
__device__ unsigned char g_maskF[NN*NN];
__device__ int   g_nbrU[NN*MAXD];
__device__ int   g_cntU[NN];
__device__ int   g_nbrF[NN*MAXD];
__device__ int   g_cntF[NN];
__device__ float g_WcatU[DIN*NH*HID];
__device__ float g_WcatF[DIN*NH*HID];
__device__ float g_WhU[NN*NH*HID];
__device__ float g_WhF[NN*NH*HID];
__device__ float g_s1U[NH*NN];
__device__ float g_s2U[NH*NN];
__device__ float g_s1F[NH*NN];
__device__ float g_s2F[NH*NN];
__device__ float g_hidU[NN*NH*HID];
__device__ float g_hidF[NN*NH*HID];
__device__ float g_WhoU[NN*HID];
__device__ float g_WhoF[NN*HID];
__device__ float g_s1oU[NN];
__device__ float g_s2oU[NN];
__device__ float g_s1oF[NN];
__device__ float g_s2oF[NN];
__device__ float g_embU[NN*HID];
__device__ float g_embF[NN*HID];
__device__ float g_pair[NN*512];
__device__ float g_act0[NN*512];
__device__ float g_act1[NN*256];
__device__ float g_act2[NN*128];

// ---------------- SGEMM: double-buffered, scalar fmaf (PROVEN bitwise), z-batched ----------------
// TB=false: C[M,Nn] = A[M,K]*B[K,Nn]; TB=true: C = A[M,K]*B[Nn,K]^T
// EP: 0 none; 1 negd2 = -((sq[row]+sq[col]) - 2*acc); 2 bias+relu
// SYM: grid.x enumerates upper-tri tile pairs; writes tile; mirror written
//      COALESCED via smem staging (values identical: same epilogue expression).
// blockIdx.z in {0,1} picks the (A,B,C,sq,bias) set.
template<bool TB, int EP, bool SYM, int TBM, int TBN, int TMI, int TNI>
__launch_bounds__(256, 2)
__global__ void sgemm2(const float* __restrict__ A0, const float* __restrict__ B0,
                       float* __restrict__ C0, const float* __restrict__ sq0,
                       const float* __restrict__ bias0,
                       const float* __restrict__ A1, const float* __restrict__ B1,
                       float* __restrict__ C1, const float* __restrict__ sq1,
                       const float* __restrict__ bias1,
                       int M, int Nn, int Kk, int lda, int ldb, int ldc)
{
    static_assert((TBM/TMI)*(TBN/TNI) == 256, "thread count");
    const float* A    = blockIdx.z ? A1 : A0;
    const float* B    = blockIdx.z ? B1 : B0;
    float*       C    = blockIdx.z ? C1 : C0;
    const float* sq   = blockIdx.z ? sq1 : sq0;
    const float* bias = blockIdx.z ? bias1 : bias0;

    __shared__ float As[2][BKK][TBM+4];
    __shared__ float Bs[2][BKK][TBN+4];
    const int tid = threadIdx.x;
    int bx = blockIdx.x, by = blockIdx.y;
    if (SYM) {
        int nb = M / TBM;
        int idx = blockIdx.x, bi = 0;
        while (idx >= nb - bi) { idx -= nb - bi; bi++; }
        by = bi; bx = bi + idx;
    }
    const int m0 = by * TBM, n0 = bx * TBN;
    const int tm = (tid / (TBN/TNI)) * TMI;
    const int tn = (tid % (TBN/TNI)) * TNI;

    const int AIT = TBM*BKK/4/256 > 0 ? TBM*BKK/4/256 : 1;
    const int BIT = TBN*BKK/4/256 > 0 ? TBN*BKK/4/256 : 1;
    float4 ra[AIT], rb[BIT];

    auto LOADA = [&](int k0) {
#pragma unroll
        for (int it = 0; it < AIT; it++) {
            int q = tid + it*256;
            int r = q >> 2, c4 = (q & 3) * 4;
            ra[it] = *(const float4*)(A + (size_t)(m0 + r)*lda + k0 + c4);
        }
    };
    auto STOREA = [&](int buf) {
#pragma unroll
        for (int it = 0; it < AIT; it++) {
            int q = tid + it*256;
            int r = q >> 2, c4 = (q & 3) * 4;
            As[buf][c4+0][r] = ra[it].x; As[buf][c4+1][r] = ra[it].y;
            As[buf][c4+2][r] = ra[it].z; As[buf][c4+3][r] = ra[it].w;
        }
    };
    auto LOADB = [&](int k0) {
#pragma unroll
        for (int it = 0; it < BIT; it++) {
            int q = tid + it*256;
            if (!TB) {
                int r = q / (TBN/4), cn = (q % (TBN/4)) * 4;
                rb[it] = *(const float4*)(B + (size_t)(k0 + r)*ldb + n0 + cn);
            } else {
                int r = q >> 2, c4 = (q & 3) * 4;
                rb[it] = *(const float4*)(B + (size_t)(n0 + r)*ldb + k0 + c4);
            }
        }
    };
    auto STOREB = [&](int buf) {
#pragma unroll
        for (int it = 0; it < BIT; it++) {
            int q = tid + it*256;
            if (!TB) {
                int r = q / (TBN/4), cn = (q % (TBN/4)) * 4;
                Bs[buf][r][cn+0] = rb[it].x; Bs[buf][r][cn+1] = rb[it].y;
                Bs[buf][r][cn+2] = rb[it].z; Bs[buf][r][cn+3] = rb[it].w;
            } else {
                int r = q >> 2, c4 = (q & 3) * 4;
                Bs[buf][c4+0][r] = rb[it].x; Bs[buf][c4+1][r] = rb[it].y;
                Bs[buf][c4+2][r] = rb[it].z; Bs[buf][c4+3][r] = rb[it].w;
            }
        }
    };

    float acc[TMI][TNI];
#pragma unroll
    for (int i = 0; i < TMI; i++)
#pragma unroll
        for (int j = 0; j < TNI; j++) acc[i][j] = 0.f;

    auto COMPUTE = [&](int buf) {
#pragma unroll
        for (int k = 0; k < BKK; k++) {
            float a[TMI], b[TNI];
#pragma unroll
            for (int u = 0; u < TMI/4; u++) {
                float4 v = *(const float4*)&As[buf][k][tm + u*4];
                a[u*4+0] = v.x; a[u*4+1] = v.y; a[u*4+2] = v.z; a[u*4+3] = v.w;
            }
#pragma unroll
            for (int u = 0; u < TNI/4; u++) {
                float4 v = *(const float4*)&Bs[buf][k][tn + u*4];
                b[u*4+0] = v.x; b[u*4+1] = v.y; b[u*4+2] = v.z; b[u*4+3] = v.w;
            }
#pragma unroll
            for (int i = 0; i < TMI; i++)
#pragma unroll
                for (int j = 0; j < TNI; j++) acc[i][j] = fmaf(a[i], b[j], acc[i][j]);
        }
    };

    LOADA(0); LOADB(0);
    STOREA(0); STOREB(0);
    __syncthreads();
    int buf = 0;
    for (int k0 = BKK; k0 < Kk; k0 += BKK) {
        LOADA(k0); LOADB(k0);
        COMPUTE(buf);
        STOREA(buf ^ 1); STOREB(buf ^ 1);
        __syncthreads();
        buf ^= 1;
    }
    COMPUTE(buf);

    // ---- normal (row-major) writes ----
#pragma unroll
    for (int i = 0; i < TMI; i++) {
        int row = m0 + tm + i;
#pragma unroll
        for (int j = 0; j < TNI; j++) {
            int col = n0 + tn + j;
            float v = acc[i][j];
            if (EP == 1) v = -((sq[row] + sq[col]) - 2.f * v);
            if (EP == 2) { v += bias[col]; v = fmaxf(v, 0.f); }
            C[(size_t)row * ldc + col] = v;
        }
    }

    // ---- mirror writes, coalesced via smem staging (SYM off-diagonal only) ----
    if (SYM && bx != by) {
        float* Sst = &As[0][0][0];   // 2*BKK*(TBM+4) >= 32*(TBM+4) floats; compute done
#pragma unroll
        for (int p = 0; p < TBN/32; p++) {
            __syncthreads();   // smem free / previous pass consumed
            if ((tn >> 5) == p) {
#pragma unroll
                for (int j = 0; j < TNI; j++) {
                    int col = tn + j;
#pragma unroll
                    for (int i = 0; i < TMI; i++) {
                        int row = m0 + tm + i;
                        float v = acc[i][j];
                        if (EP == 1) v = -((sq[row] + sq[n0 + col]) - 2.f * v);
                        Sst[(col - p*32)*(TBM+4) + (tm + i)] = v;
                    }
                }
            }
            __syncthreads();
            for (int q = tid; q < 32*TBM; q += 256) {
                int rm = q / TBM, cm = q % TBM;
                C[(size_t)(n0 + p*32 + rm) * ldc + (m0 + cm)] = Sst[rm*(TBM+4) + cm];
            }
        }
    }
}

// ---------------- prep: z=0 rowsum-sq(user) -> sqU ; z=1 normalize(food) -> XnF ----------------
__global__ void prep_kernel(const float* __restrict__ user, float* __restrict__ sqU,
                            const float* __restrict__ food, float* __restrict__ XnF)
{
    const float* X = blockIdx.z ? food : user;
    int i = blockIdx.x, tid = threadIdx.x;
    float s = 0.f;
    for (int j = tid; j < DIN; j += 256) { float v = X[(size_t)i*DIN + j]; s = fmaf(v, v, s); }
    __shared__ float r[256];
    r[tid] = s; __syncthreads();
    for (int st = 128; st > 0; st >>= 1) { if (tid < st) r[tid] += r[tid + st]; __syncthreads(); }
    if (blockIdx.z == 0) {
        if (tid == 0) sqU[i] = r[0];
    } else {
        float nrm = sqrtf(r[0]);
        for (int j = tid; j < DIN; j += 256) XnF[(size_t)i*DIN + j] = X[(size_t)i*DIN + j] / nrm;
    }
}

// ---------------- deterministic total order: (value desc, index asc) ----------------
__device__ __forceinline__ bool better(float a, int ai, float b, int bi)
{
    return (a > b) || (a == b && ai < bi);
}

// ---------------- single-pass top-6, 256 threads, z-batched ----------------
// Local insertion-sorted top-6 per thread over 8 strided elems, then 6
// exclusion-argmax passes over 1536 candidates. Identical selection under
// the strict total order (distinct indices => no ties).
__global__ void top6_onepass(const float* __restrict__ S0, const float* __restrict__ S1,
                             int* __restrict__ oI0, float* __restrict__ oV0,
                             int* __restrict__ oI1, float* __restrict__ oV1)
{
    const float* S = blockIdx.z ? S1 : S0;
    int*   oI = blockIdx.z ? oI1 : oI0;
    float* oV = blockIdx.z ? oV1 : oV0;

    __shared__ float sv[256*TOPK];
    __shared__ int   si[256*TOPK];
    __shared__ int   ch[TOPK];
    __shared__ float rv[256];
    __shared__ int   ri[256];

    int row = blockIdx.x, tid = threadIdx.x;
    const float* Sr = S + (size_t)row * NN;

    float lv[TOPK]; int li[TOPK];
#pragma unroll
    for (int t = 0; t < TOPK; t++) { lv[t] = -FLT_MAX; li[t] = 0x7FFFFFFF; }
    for (int j = tid; j < NN; j += 256) {
        float x = Sr[j];
        if (better(x, j, lv[TOPK-1], li[TOPK-1])) {
            lv[TOPK-1] = x; li[TOPK-1] = j;
#pragma unroll
            for (int t = TOPK-1; t > 0; t--) {
                if (better(lv[t], li[t], lv[t-1], li[t-1])) {
                    float tv = lv[t]; lv[t] = lv[t-1]; lv[t-1] = tv;
                    int ti = li[t]; li[t] = li[t-1]; li[t-1] = ti;
                } else break;
            }
        }
    }
#pragma unroll
    for (int t = 0; t < TOPK; t++) { sv[tid*TOPK+t] = lv[t]; si[tid*TOPK+t] = li[t]; }
    __syncthreads();

    for (int t = 0; t < TOPK; t++) {
        float bv = -FLT_MAX; int bi = 0x7FFFFFFF;
#pragma unroll
        for (int u = 0; u < TOPK; u++) {
            int e = tid*TOPK + u;
            int cidx = si[e];
            bool used = false;
            for (int w = 0; w < t; w++) used |= (ch[w] == cidx);
            if (!used && better(sv[e], cidx, bv, bi)) { bv = sv[e]; bi = cidx; }
        }
        rv[tid] = bv; ri[tid] = bi;
        __syncthreads();
        if (tid < 32) {
#pragma unroll
            for (int o = 32; o < 256; o += 32) {
                if (better(rv[tid+o], ri[tid+o], bv, bi)) { bv = rv[tid+o]; bi = ri[tid+o]; }
            }
#pragma unroll
            for (int o = 16; o > 0; o >>= 1) {
                float ov = __shfl_down_sync(0xFFFFFFFFu, bv, o);
                int   oi = __shfl_down_sync(0xFFFFFFFFu, bi, o);
                if (better(ov, oi, bv, bi)) { bv = ov; bi = oi; }
            }
            if (tid == 0) {
                ch[t] = bi;
                oI[row*TOPK + t] = bi;
                oV[row*TOPK + t] = bv;
            }
        }
        __syncthreads();
    }
}

// ---------------- adjacency mask build, z-batched ----------------
__global__ void clear_masks()
{
    int i = blockIdx.x * blockDim.x + threadIdx.x;   // NN*NN/4 words
    ((unsigned int*)g_maskU)[i] = 0u;
    ((unsigned int*)g_maskF)[i] = 0u;
}

__global__ void mark_kernel2(const int* __restrict__ idx0, const float* __restrict__ val0,
                             unsigned char* __restrict__ mask0,
                             const int* __restrict__ idx1, const float* __restrict__ val1,
                             unsigned char* __restrict__ mask1)
{
    const int*   idx  = blockIdx.z ? idx1 : idx0;
    const float* val  = blockIdx.z ? val1 : val0;
    unsigned char* mask = blockIdx.z ? mask1 : mask0;
    int needPos = blockIdx.z;   // food (z=1) requires positive sim
    int i = blockIdx.x * blockDim.x + threadIdx.x;
    if (i >= NN) return;
#pragma unroll
    for (int t = 0; t < TOPK; t++) {
        int j = idx[i*TOPK + t];
        if (j == i) continue;
        if (needPos && !(val[i*TOPK + t] > 0.f)) continue;
        mask[(size_t)i*NN + j] = 1;
        mask[(size_t)j*NN + i] = 1;
    }
}

// ---------------- neighbor list: warp-ballot compaction (ascending), z-batched ----------------
__global__ void collect_kernel2(const unsigned char* __restrict__ mask0,
                                int* __restrict__ nbr0, int* __restrict__ cnt0,
                                const unsigned char* __restrict__ mask1,
                                int* __restrict__ nbr1, int* __restrict__ cnt1)
{
    const unsigned char* mask = blockIdx.z ? mask1 : mask0;
    int* nbr = blockIdx.z ? nbr1 : nbr0;
    int* cnt = blockIdx.z ? cnt1 : cnt0;
    int warp = (blockIdx.x * blockDim.x + threadIdx.x) >> 5;
    int lane = threadIdx.x & 31;
    if (warp >= NN) return;
    const unsigned char* mr = mask + (size_t)warp * NN;
    int c = 0;
    for (int base = 0; base < NN; base += 32) {
        bool m = mr[base + lane] != 0;
        unsigned b = __ballot_sync(0xFFFFFFFFu, m);
        if (m) nbr[(size_t)warp*MAXD + c + __popc(b & ((1u << lane) - 1u))] = base + lane;
        c += __popc(b);
    }
    if (lane == 0) cnt[warp] = c;
}

// ---------------- sparse attention + aggregate + elu (hub-safe, PROVEN), z-batched ----------------
__global__ void att_agg2(const float* __restrict__ Wh0, const float* __restrict__ s10,
                         const float* __restrict__ s20, const int* __restrict__ nbr0,
                         const int* __restrict__ cnt0, float* __restrict__ out0,
                         const float* __restrict__ Wh1, const float* __restrict__ s11,
                         const float* __restrict__ s21, const int* __restrict__ nbr1,
                         const int* __restrict__ cnt1, float* __restrict__ out1,
                         int rowStride, int nheads)
{
    const float* Wh = blockIdx.z ? Wh1 : Wh0;
    const float* s1 = blockIdx.z ? s11 : s10;
    const float* s2 = blockIdx.z ? s21 : s20;
    const int* nbr  = blockIdx.z ? nbr1 : nbr0;
    const int* cnt  = blockIdx.z ? cnt1 : cnt0;
    float* out      = blockIdx.z ? out1 : out0;

    __shared__ int   sidx[MAXD];       // 8 KB
    __shared__ float sw[NH][MAXD];     // 32 KB
    __shared__ float hs[NH];
    int i = blockIdx.x, tid = threadIdx.x;
    int wid = tid >> 5, lane = tid & 31;
    int c = cnt[i];

    for (int t = tid; t < c; t += 256) sidx[t] = nbr[(size_t)i*MAXD + t];
    __syncthreads();

    for (int q = tid; q < nheads*c; q += 256) {
        int h = q / c, t = q - h*c;
        float e = s1[h*NN + i] + s2[h*NN + sidx[t]];
        sw[h][t] = (e >= 0.f) ? e : 0.2f * e;
    }
    __syncthreads();

    if (wid < nheads) {
        int h = wid;
        float m = -FLT_MAX;
        for (int t = lane; t < c; t += 32) m = fmaxf(m, sw[h][t]);
#pragma unroll
        for (int o = 16; o > 0; o >>= 1) m = fmaxf(m, __shfl_xor_sync(0xFFFFFFFFu, m, o));
        float s = 0.f;
        for (int t = lane; t < c; t += 32) { float ex = expf(sw[h][t] - m); sw[h][t] = ex; s += ex; }
#pragma unroll
        for (int o = 16; o > 0; o >>= 1) s += __shfl_xor_sync(0xFFFFFFFFu, s, o);
        if (lane == 0) hs[h] = s;
    }
    __syncthreads();

    for (int q = tid; q < nheads*c; q += 256) {
        int h = q / c, t = q - h*c;
        sw[h][t] /= hs[h];
    }
    __syncthreads();

    for (int h = 0; h < nheads; h++) {
        float acc = 0.f;
#pragma unroll 4
        for (int t = 0; t < c; t++)
            acc = fmaf(sw[h][t], Wh[(size_t)sidx[t]*rowStride + h*HID + tid], acc);
        out[(size_t)i*rowStride + h*HID + tid] = (acc > 0.f) ? acc : expm1f(acc);
    }
}

// ---------------- GAT helper kernels, z-batched ----------------
__global__ void repack_W2(const float* __restrict__ W0, float* __restrict__ Wcat0,
                          const float* __restrict__ W1, float* __restrict__ Wcat1)
{
    const float* W = blockIdx.z ? W1 : W0;
    float* Wcat    = blockIdx.z ? Wcat1 : Wcat0;
    int i = blockIdx.x * blockDim.x + threadIdx.x;
    if (i >= DIN*NH*HID) return;
    int d = i / (NH*HID);
    int r = i % (NH*HID);
    int h = r / HID;
    int f = r % HID;
    Wcat[i] = W[(size_t)h*DIN*HID + (size_t)d*HID + f];
}

__global__ void s1s2_kernel2(const float* __restrict__ WhA, const float* __restrict__ aA,
                             float* __restrict__ s1A, float* __restrict__ s2A,
                             const float* __restrict__ WhB, const float* __restrict__ aB,
                             float* __restrict__ s1B, float* __restrict__ s2B,
                             int rowStride)
{
    const float* Wh = blockIdx.z ? WhB : WhA;
    const float* a  = blockIdx.z ? aB : aA;
    float* s1 = blockIdx.z ? s1B : s1A;
    float* s2 = blockIdx.z ? s2B : s2A;
    int i = blockIdx.x, h = blockIdx.y, f = threadIdx.x;   // 256 threads
    float w = Wh[(size_t)i*rowStride + h*HID + f];
    float v1 = w * a[h*2*HID + f];
    float v2 = w * a[h*2*HID + HID + f];
    __shared__ float r1[256], r2[256];
    r1[f] = v1; r2[f] = v2; __syncthreads();
    for (int st = 128; st > 0; st >>= 1) {
        if (f < st) { r1[f] += r1[f+st]; r2[f] += r2[f+st]; }
        __syncthreads();
    }
    if (f == 0) { s1[h*NN + i] = r1[0]; s2[h*NN + i] = r2[0]; }
}

// ---------------- MLP pieces (PROVEN) ----------------
__global__ void concat_kernel()
{
    int i = blockIdx.x, c = threadIdx.x;   // 512 threads
    g_pair[(size_t)i*512 + c] = (c < HID) ? g_embU[(size_t)i*HID + c]
                                          : g_embF[(size_t)i*HID + (c - HID)];
}

__global__ void mlp_final_kernel(const float* __restrict__ act, const float* __restrict__ W,
                                 const float* __restrict__ b, float* __restrict__ out)
{
    int i = blockIdx.x, tid = threadIdx.x;   // 128 threads
    float v = act[(size_t)i*128 + tid] * W[tid];
    __shared__ float r[128];
    r[tid] = v; __syncthreads();
    for (int st = 64; st > 0; st >>= 1) { if (tid < st) r[tid] += r[tid+st]; __syncthreads(); }
    if (tid == 0) out[i] = r[0] + b[0];
}

// ---------------- host launch ----------------
template <typename T>
static T* sym(const void* s)
{
    void* p = nullptr;
    cudaGetSymbolAddress(&p, s);
    return (T*)p;
}

extern "C" void kernel_launch(void* const* d_in, const int* in_sizes, int n_in,
                              void* d_out, int out_size)
{
    const float* user_nodes = (const float*)d_in[0];
    const float* food_nodes = (const float*)d_in[1];
    const float* user_W_h   = (const float*)d_in[2];
    const float* user_a_h   = (const float*)d_in[3];
    const float* user_W_o   = (const float*)d_in[4];
    const float* user_a_o   = (const float*)d_in[5];
    const float* food_W_h   = (const float*)d_in[6];
    const float* food_a_h   = (const float*)d_in[7];
    const float* food_W_o   = (const float*)d_in[8];
    const float* food_a_o   = (const float*)d_in[9];
    const float* mlp_W0 = (const float*)d_in[10];
    const float* mlp_b0 = (const float*)d_in[11];
    const float* mlp_W1 = (const float*)d_in[12];
    const float* mlp_b1 = (const float*)d_in[13];
    const float* mlp_W2 = (const float*)d_in[14];
    const float* mlp_b2 = (const float*)d_in[15];
    const float* mlp_W3 = (const float*)d_in[16];
    const float* mlp_b3 = (const float*)d_in[17];
    float* out = (float*)d_out;

    float* pZero  = sym<float>(g_zero);
    float* pSqU   = sym<float>(g_sqU);
    float* pXnF   = sym<float>(g_XnF);
    float* pSimU  = sym<float>(g_simU);
    float* pSimF  = sym<float>(g_simF);
    int*   pTidxU = sym<int>(g_tidxU);
    float* pTvalU = sym<float>(g_tvalU);
    int*   pTidxF = sym<int>(g_tidxF);
    float* pTvalF = sym<float>(g_tvalF);
    unsigned char* pMaskU = sym<unsigned char>(g_maskU);
    unsigned char* pMaskF = sym<unsigned char>(g_maskF);
    int*   pNbrU = sym<int>(g_nbrU);
    int*   pCntU = sym<int>(g_cntU);
    int*   pNbrF = sym<int>(g_nbrF);
    int*   pCntF = sym<int>(g_cntF);
    float* pWcatU = sym<float>(g_WcatU);
    float* pWcatF = sym<float>(g_WcatF);
    float* pWhU  = sym<float>(g_WhU);
    float* pWhF  = sym<float>(g_WhF);
    float* pS1U  = sym<float>(g_s1U);
    float* pS2U  = sym<float>(g_s2U);
    float* pS1F  = sym<float>(g_s1F);
    float* pS2F  = sym<float>(g_s2F);
    float* pHidU = sym<float>(g_hidU);
    float* pHidF = sym<float>(g_hidF);
    float* pWhoU = sym<float>(g_WhoU);
    float* pWhoF = sym<float>(g_WhoF);
    float* pS1oU = sym<float>(g_s1oU);
    float* pS2oU = sym<float>(g_s2oU);
    float* pS1oF = sym<float>(g_s1oF);
    float* pS2oF = sym<float>(g_s2oF);
    float* pEmbU = sym<float>(g_embU);
    float* pEmbF = sym<float>(g_embF);
    float* pPair = sym<float>(g_pair);
    float* pAct0 = sym<float>(g_act0);
    float* pAct1 = sym<float>(g_act1);
    float* pAct2 = sym<float>(g_act2);

    const int NTRI = (NN/128) * (NN/128 + 1) / 2;   // 136 upper-tri tiles

    // ---- graph build ----
    prep_kernel<<<dim3(NN,1,2), 256>>>(user_nodes, pSqU, food_nodes, pXnF);
    // batched sims: z=0 user euclid (-d^2), z=1 food cosine scaled by exact 2x (sq=0)
    sgemm2<true, 1, true, 128,128,8,8><<<dim3(NTRI,1,2), 256>>>(
        user_nodes, user_nodes, pSimU, pSqU, nullptr,
        pXnF,       pXnF,       pSimF, pZero, nullptr,
        NN, NN, DIN, DIN, DIN, NN);
    top6_onepass<<<dim3(NN,1,2), 256>>>(pSimU, pSimF, pTidxU, pTvalU, pTidxF, pTvalF);

    clear_masks<<<(NN*NN/4)/256, 256>>>();
    mark_kernel2<<<dim3((NN+255)/256,1,2), 256>>>(pTidxU, pTvalU, pMaskU,
                                                  pTidxF, pTvalF, pMaskF);
    collect_kernel2<<<dim3(NN*32/256,1,2), 256>>>(pMaskU, pNbrU, pCntU,
                                                  pMaskF, pNbrF, pCntF);

    // ---- GAT hidden layer (user & food batched) ----
    repack_W2<<<dim3((DIN*NH*HID+255)/256,1,2), 256>>>(user_W_h, pWcatU, food_W_h, pWcatF);
    sgemm2<false, 0, false, 128,128,8,8><<<dim3((NH*HID)/128, NN/128, 2), 256>>>(
        user_nodes, pWcatU, pWhU, nullptr, nullptr,
        food_nodes, pWcatF, pWhF, nullptr, nullptr,
        NN, NH*HID, DIN, DIN, NH*HID, NH*HID);
    s1s2_kernel2<<<dim3(NN, NH, 2), 256>>>(pWhU, user_a_h, pS1U, pS2U,
                                           pWhF, food_a_h, pS1F, pS2F, NH*HID);
    att_agg2<<<dim3(NN,1,2), 256>>>(pWhU, pS1U, pS2U, pNbrU, pCntU, pHidU,
                                    pWhF, pS1F, pS2F, pNbrF, pCntF, pHidF,
                                    NH*HID, NH);

    // ---- GAT output layer (user & food batched) ----
    sgemm2<false, 0, false, 64,64,4,4><<<dim3(HID/64, NN/64, 2), 256>>>(
        pHidU, user_W_o, pWhoU, nullptr, nullptr,
        pHidF, food_W_o, pWhoF, nullptr, nullptr,
        NN, HID, NH*HID, NH*HID, HID, HID);
    s1s2_kernel2<<<dim3(NN, 1, 2), 256>>>(pWhoU, user_a_o, pS1oU, pS2oU,
                                          pWhoF, food_a_o, pS1oF, pS2oF, HID);
    att_agg2<<<dim3(NN,1,2), 256>>>(pWhoU, pS1oU, pS2oU, pNbrU, pCntU, pEmbU,
                                    pWhoF, pS1oF, pS2oF, pNbrF, pCntF, pEmbF,
                                    HID, 1);

    // ---- MLP ----
    concat_kernel<<<NN, 512>>>();
    sgemm2<false, 2, false, 64,64,4,4><<<dim3(512/64, NN/64, 1), 256>>>(
        pPair, mlp_W0, pAct0, nullptr, mlp_b0,
        pPair, mlp_W0, pAct0, nullptr, mlp_b0,
        NN, 512, 512, 512, 512, 512);
    sgemm2<false, 2, false, 64,64,4,4><<<dim3(256/64, NN/64, 1), 256>>>(
        pAct0, mlp_W1, pAct1, nullptr, mlp_b1,
        pAct0, mlp_W1, pAct1, nullptr, mlp_b1,
        NN, 256, 512, 512, 256, 256);
    sgemm2<false, 2, false, 64,64,4,4><<<dim3(128/64, NN/64, 1), 256>>>(
        pAct1, mlp_W2, pAct2, nullptr, mlp_b2,
        pAct1, mlp_W2, pAct2, nullptr, mlp_b2,
        NN, 128, 256, 256, 128, 128);
    mlp_final_kernel<<<NN, 128>>>(pAct2, mlp_W3, mlp_b3, out);
}